// round 1
// baseline (speedup 1.0000x reference)
#include <cuda_runtime.h>
#include <stdint.h>
#include <math.h>

#define NB 64
#define NP 8732
#define NC 81
#define NO 32
#define THRESH 0.5f
#define NPR 3

// ---------------- device scratch (no allocs allowed) ----------------
__device__ float g_ceneg[NB * NP];   // CE for negatives, 0 for positives
__device__ int   g_lab[NB * NP];     // matched label per prior
__device__ int   g_npos[NB];
__device__ float g_loc_sum;
__device__ float g_pos_sum;
__device__ float g_hard_sum;
__device__ int   g_npos_total;

__global__ void k_init() {
    g_loc_sum = 0.f; g_pos_sum = 0.f; g_hard_sum = 0.f; g_npos_total = 0;
}

// ---------------- kernel 1: matching + loc loss ----------------
// one CTA per batch, 1024 threads; everything SMEM-resident
__global__ __launch_bounds__(1024) void k_match(
    const float* __restrict__ pred_locs,   // [B,P,4]
    const float* __restrict__ boxes,       // [B,O,4] xy
    const int*   __restrict__ labels_i32,  // int32 or int64 (detected)
    const float* __restrict__ priors)      // [P,4] cxcy
{
    __shared__ float s_ovfp[NP];
    __shared__ unsigned char s_obj[NP];
    __shared__ float s_box[NO * 4];
    __shared__ int   s_lab[NO];
    __shared__ unsigned long long s_key[NO];
    __shared__ float s_rf[32];
    __shared__ int   s_ri[32];

    const int b = blockIdx.x, tid = threadIdx.x, nt = blockDim.x;
    // int64 detection: high word of labels[0] is 0 iff int64 (labels in [1,81))
    const bool lab64 = (labels_i32[1] == 0);

    if (tid < NO * 4) s_box[tid] = boxes[b * NO * 4 + tid];
    if (tid < NO) {
        s_lab[tid] = lab64 ? labels_i32[(b * NO + tid) * 2] : labels_i32[b * NO + tid];
        s_key[tid] = 0ull;
    }
    __syncthreads();

    // Phase A: per-prior best object (first-max) + per-object best prior (min-index tie)
    for (int p = tid; p < NP; p += nt) {
        const float pcx = priors[p * 4 + 0], pcy = priors[p * 4 + 1];
        const float pw  = priors[p * 4 + 2], ph  = priors[p * 4 + 3];
        const float px0 = pcx - pw * 0.5f, py0 = pcy - ph * 0.5f;
        const float px1 = pcx + pw * 0.5f, py1 = pcy + ph * 0.5f;
        const float parea = (px1 - px0) * (py1 - py0);
        float best = -1.f; int bi = 0;
        #pragma unroll
        for (int o = 0; o < NO; ++o) {
            const float bx0 = s_box[o*4+0], by0 = s_box[o*4+1];
            const float bx1 = s_box[o*4+2], by1 = s_box[o*4+3];
            float iw = fminf(bx1, px1) - fmaxf(bx0, px0); iw = fmaxf(iw, 0.f);
            float ih = fminf(by1, py1) - fmaxf(by0, py0); ih = fmaxf(ih, 0.f);
            const float inter = iw * ih;
            const float ba = (bx1 - bx0) * (by1 - by0);
            const float iou = inter / (ba + parea - inter);
            if (iou > best) { best = iou; bi = o; }  // strict > -> first max
            // packed key: higher iou wins; tie -> smaller p wins
            const unsigned long long key =
                ((unsigned long long)__float_as_uint(iou) << 32) |
                (unsigned)(0x7fffffff - p);
            if (key > s_key[o]) atomicMax(&s_key[o], key);
        }
        s_ovfp[p] = best;
        s_obj[p]  = (unsigned char)bi;
    }
    __syncthreads();

    // Phase B: force-match each object's best prior (sequential, last-write-wins)
    if (tid == 0) {
        for (int o = 0; o < NO; ++o) {
            const int p = 0x7fffffff - (int)(unsigned)(s_key[o] & 0xffffffffull);
            s_obj[p] = (unsigned char)o;
            s_ovfp[p] = 1.0f;
        }
    }
    __syncthreads();

    // Phase C: labels, n_pos, loc L1 on positives
    float locsum = 0.f; int npos = 0;
    for (int p = tid; p < NP; p += nt) {
        const float ov = s_ovfp[p];
        const int o = s_obj[p];
        const int lab = (ov < THRESH) ? 0 : s_lab[o];
        g_lab[b * NP + p] = lab;
        if (lab != 0) {
            ++npos;
            const float bx0 = s_box[o*4+0], by0 = s_box[o*4+1];
            const float bx1 = s_box[o*4+2], by1 = s_box[o*4+3];
            const float cx = (bx0 + bx1) * 0.5f, cy = (by0 + by1) * 0.5f;
            const float w = bx1 - bx0, h = by1 - by0;
            const float pcx = priors[p*4+0], pcy = priors[p*4+1];
            const float pw  = priors[p*4+2], ph  = priors[p*4+3];
            const float g0 = (cx - pcx) / (pw / 10.0f);
            const float g1 = (cy - pcy) / (ph / 10.0f);
            const float g2 = logf(w / pw) * 5.0f;
            const float g3 = logf(h / ph) * 5.0f;
            const float* pl = pred_locs + (size_t)(b * NP + p) * 4;
            locsum += fabsf(pl[0]-g0) + fabsf(pl[1]-g1) + fabsf(pl[2]-g2) + fabsf(pl[3]-g3);
        }
    }
    // block reduce
    #pragma unroll
    for (int off = 16; off; off >>= 1) {
        locsum += __shfl_xor_sync(0xffffffffu, locsum, off);
        npos   += __shfl_xor_sync(0xffffffffu, npos, off);
    }
    const int w = tid >> 5, l = tid & 31;
    if (l == 0) { s_rf[w] = locsum; s_ri[w] = npos; }
    __syncthreads();
    if (tid < 32) {
        float f = (tid < (nt >> 5)) ? s_rf[tid] : 0.f;
        int   c = (tid < (nt >> 5)) ? s_ri[tid] : 0;
        #pragma unroll
        for (int off = 16; off; off >>= 1) {
            f += __shfl_xor_sync(0xffffffffu, f, off);
            c += __shfl_xor_sync(0xffffffffu, c, off);
        }
        if (tid == 0) {
            g_npos[b] = c;
            atomicAdd(&g_npos_total, c);
            atomicAdd(&g_loc_sum, f);
        }
    }
}

// ---------------- kernel 2: per-prior cross entropy (HBM-bound) ----------------
// warp per prior; 81 = 32 + 32 + 17
__global__ __launch_bounds__(256) void k_ce(const float* __restrict__ scores)
{
    const int gw = (int)((blockIdx.x * blockDim.x + threadIdx.x) >> 5);
    const int lane = threadIdx.x & 31;
    if (gw >= NB * NP) return;
    const float* row = scores + (size_t)gw * NC;
    const float x0 = row[lane];
    const float x1 = row[lane + 32];
    const float x2 = (lane < NC - 64) ? row[lane + 64] : -3.0e38f;
    float m = fmaxf(fmaxf(x0, x1), x2);
    #pragma unroll
    for (int off = 16; off; off >>= 1)
        m = fmaxf(m, __shfl_xor_sync(0xffffffffu, m, off));
    float s = __expf(x0 - m) + __expf(x1 - m) + ((lane < NC - 64) ? __expf(x2 - m) : 0.f);
    #pragma unroll
    for (int off = 16; off; off >>= 1)
        s += __shfl_xor_sync(0xffffffffu, s, off);
    const int lab = g_lab[gw];  // uniform across warp
    float sl;
    if (lab < 32)      sl = __shfl_sync(0xffffffffu, x0, lab);
    else if (lab < 64) sl = __shfl_sync(0xffffffffu, x1, lab - 32);
    else               sl = __shfl_sync(0xffffffffu, x2, lab - 64);
    const float ce = m + logf(s) - sl;
    if (lane == 0) {
        if (lab != 0) {
            atomicAdd(&g_pos_sum, ce);
            g_ceneg[gw] = 0.f;
        } else {
            g_ceneg[gw] = ce;
        }
    }
}

// ---------------- kernel 3: exact top-k sum via MSB radix select ----------------
// one CTA per batch, 512 threads. ce >= 0 so float bits are order-preserving.
__global__ __launch_bounds__(512) void k_hardneg()
{
    __shared__ float s_ce[NP];
    __shared__ unsigned s_cnt[256];
    __shared__ float s_sum[256];
    __shared__ unsigned sh_prefix;
    __shared__ int   sh_rem;
    __shared__ float sh_top;

    const int b = blockIdx.x, tid = threadIdx.x, nt = blockDim.x;
    for (int p = tid; p < NP; p += nt) s_ce[p] = g_ceneg[b * NP + p];
    const int k = NPR * g_npos[b];
    if (tid == 0) { sh_prefix = 0u; sh_rem = k; sh_top = 0.f; }
    __syncthreads();

    if (k <= 0) return;

    if (k >= NP) {
        // all ranks selected: sum everything
        float acc = 0.f;
        for (int p = tid; p < NP; p += nt) acc += s_ce[p];
        #pragma unroll
        for (int off = 16; off; off >>= 1) acc += __shfl_xor_sync(0xffffffffu, acc, off);
        __shared__ float s_r[16];
        if ((tid & 31) == 0) s_r[tid >> 5] = acc;
        __syncthreads();
        if (tid == 0) {
            float t = 0.f;
            for (int i = 0; i < (nt >> 5); ++i) t += s_r[i];
            atomicAdd(&g_hard_sum, t);
        }
        return;
    }

    for (int shift = 24; shift >= 0; shift -= 8) {
        __syncthreads();
        const int rem = sh_rem;
        const unsigned pref = sh_prefix;
        const unsigned hm = (shift == 24) ? 0u : (0xffffffffu << (shift + 8));
        for (int i = tid; i < 256; i += nt) { s_cnt[i] = 0u; s_sum[i] = 0.f; }
        __syncthreads();
        for (int p = tid; p < NP; p += nt) {
            const float v = s_ce[p];
            const unsigned bits = __float_as_uint(v);
            if ((bits & hm) == pref) {
                const unsigned bin = (bits >> shift) & 255u;
                atomicAdd(&s_cnt[bin], 1u);
                atomicAdd(&s_sum[bin], v);
            }
        }
        __syncthreads();
        // suffix scan of 256 bins (Hillis-Steele)
        for (int off = 1; off < 256; off <<= 1) {
            unsigned c = 0; float f = 0.f;
            if (tid < 256) {
                c = s_cnt[tid]; f = s_sum[tid];
                if (tid + off < 256) { c += s_cnt[tid + off]; f += s_sum[tid + off]; }
            }
            __syncthreads();
            if (tid < 256) { s_cnt[tid] = c; s_sum[tid] = f; }
            __syncthreads();
        }
        // select the bin containing the rem-th largest
        if (tid < 256) {
            const unsigned above_c = (tid < 255) ? s_cnt[tid + 1] : 0u;
            const float    above_s = (tid < 255) ? s_sum[tid + 1] : 0.f;
            if (s_cnt[tid] >= (unsigned)rem && above_c < (unsigned)rem) {
                sh_top += above_s;
                sh_rem  = rem - (int)above_c;
                sh_prefix = pref | ((unsigned)tid << shift);
            }
        }
    }
    __syncthreads();
    if (tid == 0) {
        const float kth = __uint_as_float(sh_prefix);
        atomicAdd(&g_hard_sum, sh_top + (float)sh_rem * kth);
    }
}

// ---------------- kernel 4: finalize ----------------
__global__ void k_final(float* __restrict__ out)
{
    const float np = (float)g_npos_total;
    out[0] = (g_hard_sum + g_pos_sum) / np + g_loc_sum / (np * 4.0f);
}

// ---------------- launch ----------------
extern "C" void kernel_launch(void* const* d_in, const int* in_sizes, int n_in,
                              void* d_out, int out_size)
{
    const float* pred_locs   = (const float*)d_in[0];
    const float* pred_scores = (const float*)d_in[1];
    const float* boxes       = (const float*)d_in[2];
    const int*   labels      = (const int*)d_in[3];
    const float* priors      = (const float*)d_in[4];
    float* out = (float*)d_out;

    k_init<<<1, 1>>>();
    k_match<<<NB, 1024>>>(pred_locs, boxes, labels, priors);
    const int warps = NB * NP;
    k_ce<<<(warps * 32 + 255) / 256, 256>>>(pred_scores);
    k_hardneg<<<NB, 512>>>();
    k_final<<<1, 1>>>(out);
}

// round 2
// speedup vs baseline: 2.0793x; 2.0793x over previous
#include <cuda_runtime.h>
#include <stdint.h>

#define NB 64
#define NP 8732
#define NC 81
#define NO 32
#define THRESH 0.5f
#define NPR 3
#define MCH 8
#define MTH 256
#define PCHUNK ((NP + MCH - 1) / MCH)   // 1092

// ---------------- device scratch ----------------
__device__ unsigned long long g_key[NB * NO];
__device__ float g_ovfp[NB * NP];
__device__ unsigned char g_obj[NB * NP];
__device__ int   g_lab[NB * NP];
__device__ float g_ceneg[NB * NP];
__device__ int   g_npos[NB];
__device__ float g_loc_sum, g_pos_sum, g_hard_sum;
__device__ int   g_npos_total;

// key for iou=0, prior p: low word = 0x7fffffff - p
#define KEY0 0x7fffffffull   // iou=0, p=0 (argmax of all-zero row -> first index)

__global__ void k_init() {
    const int i = blockIdx.x * blockDim.x + threadIdx.x;
    if (i < NB * NO) g_key[i] = KEY0;
    if (i < NB) g_npos[i] = 0;
    if (i == 0) { g_loc_sum = 0.f; g_pos_sum = 0.f; g_hard_sum = 0.f; g_npos_total = 0; }
}

// ---------------- matching phase A: per-prior best obj + per-obj best prior ----------------
__global__ __launch_bounds__(MTH) void k_matchA(
    const float4* __restrict__ priors4,   // [P] cxcy
    const float*  __restrict__ boxes)     // [B,O,4] xy
{
    __shared__ float s_bx0[NO], s_by0[NO], s_bx1[NO], s_by1[NO], s_ba[NO];
    __shared__ unsigned long long s_key[NO];

    const int b = blockIdx.y, chunk = blockIdx.x, tid = threadIdx.x;
    if (tid < NO) {
        const float x0 = boxes[(b*NO+tid)*4+0], y0 = boxes[(b*NO+tid)*4+1];
        const float x1 = boxes[(b*NO+tid)*4+2], y1 = boxes[(b*NO+tid)*4+3];
        s_bx0[tid] = x0; s_by0[tid] = y0; s_bx1[tid] = x1; s_by1[tid] = y1;
        s_ba[tid] = (x1 - x0) * (y1 - y0);
        s_key[tid] = KEY0;
    }
    __syncthreads();

    const int p0 = chunk * PCHUNK;
    const int p1 = (p0 + PCHUNK < NP) ? p0 + PCHUNK : NP;
    for (int p = p0 + tid; p < p1; p += MTH) {
        const float4 pr = priors4[p];
        const float px0 = pr.x - pr.z * 0.5f, py0 = pr.y - pr.w * 0.5f;
        const float px1 = pr.x + pr.z * 0.5f, py1 = pr.y + pr.w * 0.5f;
        const float parea = (px1 - px0) * (py1 - py0);
        const unsigned lowp = (unsigned)(0x7fffffff - p);
        float best = -1.f; int bi = 0;
        #pragma unroll
        for (int o = 0; o < NO; ++o) {
            float iw = fminf(s_bx1[o], px1) - fmaxf(s_bx0[o], px0); iw = fmaxf(iw, 0.f);
            float ih = fminf(s_by1[o], py1) - fmaxf(s_by0[o], py0); ih = fmaxf(ih, 0.f);
            const float inter = iw * ih;
            const float iou = __fdividef(inter, s_ba[o] + parea - inter);
            if (iou > best) { best = iou; bi = o; }
            const unsigned long long key =
                ((unsigned long long)__float_as_uint(iou) << 32) | lowp;
            if (key > s_key[o]) atomicMax(&s_key[o], key);   // monotonic: stale read never skips
        }
        g_ovfp[b*NP+p] = best;
        g_obj[b*NP+p]  = (unsigned char)bi;
    }
    __syncthreads();
    if (tid < NO && s_key[tid] != KEY0) atomicMax(&g_key[b*NO+tid], s_key[tid]);
}

// ---------------- phase B: force-match, highest-o wins on duplicate priors ----------------
__global__ void k_force() {
    const int b = blockIdx.x, lane = threadIdx.x;   // 32 threads
    const unsigned long long key = g_key[b*NO + lane];
    const int p = 0x7fffffff - (int)(unsigned)(key & 0xffffffffull);
    const unsigned m = __match_any_sync(0xffffffffu, p);
    if (lane == 31 - __clz(m)) {   // last .at[].set wins -> highest o
        g_obj[b*NP+p]  = (unsigned char)lane;
        g_ovfp[b*NP+p] = 1.0f;
    }
}

// ---------------- phase C: labels, n_pos, loc L1 ----------------
__global__ __launch_bounds__(MTH) void k_matchC(
    const float4* __restrict__ predloc4,  // [B*P]
    const float*  __restrict__ boxes,
    const int*    __restrict__ labels_i32,
    const float4* __restrict__ priors4)
{
    __shared__ float s_bx0[NO], s_by0[NO], s_bx1[NO], s_by1[NO];
    __shared__ int s_lab[NO];
    __shared__ float s_rf[8]; __shared__ int s_ri[8];

    const int b = blockIdx.y, chunk = blockIdx.x, tid = threadIdx.x;
    const bool lab64 = (labels_i32[1] == 0);
    if (tid < NO) {
        s_bx0[tid] = boxes[(b*NO+tid)*4+0]; s_by0[tid] = boxes[(b*NO+tid)*4+1];
        s_bx1[tid] = boxes[(b*NO+tid)*4+2]; s_by1[tid] = boxes[(b*NO+tid)*4+3];
        s_lab[tid] = lab64 ? labels_i32[(b*NO+tid)*2] : labels_i32[b*NO+tid];
    }
    __syncthreads();

    const int p0 = chunk * PCHUNK;
    const int p1 = (p0 + PCHUNK < NP) ? p0 + PCHUNK : NP;
    float locsum = 0.f; int npos = 0;
    for (int p = p0 + tid; p < p1; p += MTH) {
        const float ov = g_ovfp[b*NP+p];
        const int o = g_obj[b*NP+p];
        const int lab = (ov < THRESH) ? 0 : s_lab[o];
        g_lab[b*NP+p] = lab;
        if (lab != 0) {
            ++npos;
            const float bx0 = s_bx0[o], by0 = s_by0[o], bx1 = s_bx1[o], by1 = s_by1[o];
            const float cx = (bx0 + bx1) * 0.5f, cy = (by0 + by1) * 0.5f;
            const float w = bx1 - bx0, h = by1 - by0;
            const float4 pr = priors4[p];
            const float g0 = (cx - pr.x) / (pr.z * 0.1f);
            const float g1 = (cy - pr.y) / (pr.w * 0.1f);
            const float g2 = logf(w / pr.z) * 5.0f;
            const float g3 = logf(h / pr.w) * 5.0f;
            const float4 pl = predloc4[b*NP+p];
            locsum += fabsf(pl.x-g0) + fabsf(pl.y-g1) + fabsf(pl.z-g2) + fabsf(pl.w-g3);
        }
    }
    #pragma unroll
    for (int off = 16; off; off >>= 1) {
        locsum += __shfl_xor_sync(0xffffffffu, locsum, off);
        npos   += __shfl_xor_sync(0xffffffffu, npos, off);
    }
    if ((tid & 31) == 0) { s_rf[tid>>5] = locsum; s_ri[tid>>5] = npos; }
    __syncthreads();
    if (tid == 0) {
        float f = 0.f; int c = 0;
        #pragma unroll
        for (int i = 0; i < MTH/32; ++i) { f += s_rf[i]; c += s_ri[i]; }
        atomicAdd(&g_loc_sum, f);
        atomicAdd(&g_npos[b], c);
        atomicAdd(&g_npos_total, c);
    }
}

// ---------------- cross entropy: warp per prior ----------------
__global__ __launch_bounds__(256) void k_ce(const float* __restrict__ scores)
{
    const int gw = (int)((blockIdx.x * blockDim.x + threadIdx.x) >> 5);
    const int lane = threadIdx.x & 31;
    if (gw >= NB * NP) return;
    const float* row = scores + (size_t)gw * NC;
    const float x0 = row[lane];
    const float x1 = row[lane + 32];
    const float x2 = (lane < NC - 64) ? row[lane + 64] : -3.0e38f;
    float m = fmaxf(fmaxf(x0, x1), x2);
    #pragma unroll
    for (int off = 16; off; off >>= 1)
        m = fmaxf(m, __shfl_xor_sync(0xffffffffu, m, off));
    float s = __expf(x0 - m) + __expf(x1 - m) + ((lane < NC - 64) ? __expf(x2 - m) : 0.f);
    #pragma unroll
    for (int off = 16; off; off >>= 1)
        s += __shfl_xor_sync(0xffffffffu, s, off);
    const int lab = g_lab[gw];
    float sl;
    if (lab < 32)      sl = __shfl_sync(0xffffffffu, x0, lab);
    else if (lab < 64) sl = __shfl_sync(0xffffffffu, x1, lab - 32);
    else               sl = __shfl_sync(0xffffffffu, x2, lab - 64);
    const float ce = m + __logf(s) - sl;
    if (lane == 0) {
        if (lab != 0) { atomicAdd(&g_pos_sum, ce); g_ceneg[gw] = 0.f; }
        else          { g_ceneg[gw] = ce; }
    }
}

// ---------------- exact top-k sum: counts-only radix select, warp-aggregated ----------------
__global__ __launch_bounds__(512) void k_hardneg()
{
    __shared__ float s_ce[NP];
    __shared__ int s_cnt[256];
    __shared__ unsigned sh_prefix;
    __shared__ int sh_rem;
    __shared__ float s_r[16];

    const int b = blockIdx.x, tid = threadIdx.x, nt = 512, lane = tid & 31;
    for (int p = tid; p < NP; p += nt) s_ce[p] = g_ceneg[b*NP+p];
    const int k = NPR * g_npos[b];
    if (tid == 0) { sh_prefix = 0u; sh_rem = k; }
    __syncthreads();
    if (k <= 0) return;

    if (k >= NP) {
        float acc = 0.f;
        for (int p = tid; p < NP; p += nt) acc += s_ce[p];
        #pragma unroll
        for (int off = 16; off; off >>= 1) acc += __shfl_xor_sync(0xffffffffu, acc, off);
        if (lane == 0) s_r[tid >> 5] = acc;
        __syncthreads();
        if (tid == 0) {
            float t = 0.f;
            #pragma unroll
            for (int i = 0; i < 16; ++i) t += s_r[i];
            atomicAdd(&g_hard_sum, t);
        }
        return;
    }

    for (int shift = 24; shift >= 0; shift -= 8) {
        const unsigned pref = sh_prefix;
        const int rem = sh_rem;
        const unsigned hm = (shift == 24) ? 0u : (0xffffffffu << (shift + 8));
        if (tid < 256) s_cnt[tid] = 0;
        __syncthreads();

        for (int base = 0; base < NP; base += nt) {
            const int p = base + tid;
            unsigned bin = 0xffffffffu;
            if (p < NP) {
                const unsigned bits = __float_as_uint(s_ce[p]);
                if ((bits & hm) == pref) bin = (bits >> shift) & 255u;
            }
            const unsigned mm = __match_any_sync(0xffffffffu, bin);
            if (bin != 0xffffffffu && lane == (unsigned)(__ffs(mm) - 1))
                atomicAdd(&s_cnt[bin], __popc(mm));
        }
        __syncthreads();

        // suffix scan (counts >= bin)
        for (int off = 1; off < 256; off <<= 1) {
            int c = 0;
            if (tid < 256) { c = s_cnt[tid]; if (tid + off < 256) c += s_cnt[tid + off]; }
            __syncthreads();
            if (tid < 256) s_cnt[tid] = c;
            __syncthreads();
        }
        if (tid < 256) {
            const int ge = s_cnt[tid];
            const int gt = (tid < 255) ? s_cnt[tid + 1] : 0;
            if (ge >= rem && gt < rem) {
                sh_rem = rem - gt;
                sh_prefix = pref | ((unsigned)tid << shift);
            }
        }
        __syncthreads();
    }

    const float kth = __uint_as_float(sh_prefix);
    const int rem = sh_rem;
    float acc = 0.f;
    for (int p = tid; p < NP; p += nt) { const float v = s_ce[p]; if (v > kth) acc += v; }
    #pragma unroll
    for (int off = 16; off; off >>= 1) acc += __shfl_xor_sync(0xffffffffu, acc, off);
    if (lane == 0) s_r[tid >> 5] = acc;
    __syncthreads();
    if (tid == 0) {
        float t = 0.f;
        #pragma unroll
        for (int i = 0; i < 16; ++i) t += s_r[i];
        atomicAdd(&g_hard_sum, t + (float)rem * kth);
    }
}

__global__ void k_final(float* __restrict__ out)
{
    const float np = (float)g_npos_total;
    out[0] = (g_hard_sum + g_pos_sum) / np + g_loc_sum / (np * 4.0f);
}

// ---------------- launch ----------------
extern "C" void kernel_launch(void* const* d_in, const int* in_sizes, int n_in,
                              void* d_out, int out_size)
{
    const float* pred_locs   = (const float*)d_in[0];
    const float* pred_scores = (const float*)d_in[1];
    const float* boxes       = (const float*)d_in[2];
    const int*   labels      = (const int*)d_in[3];
    const float* priors      = (const float*)d_in[4];
    float* out = (float*)d_out;

    k_init<<<(NB*NO + 255)/256, 256>>>();
    dim3 mg(MCH, NB);
    k_matchA<<<mg, MTH>>>((const float4*)priors, boxes);
    k_force<<<NB, 32>>>();
    k_matchC<<<mg, MTH>>>((const float4*)pred_locs, boxes, labels, (const float4*)priors);
    const int warps = NB * NP;
    k_ce<<<(warps * 32 + 255) / 256, 256>>>(pred_scores);
    k_hardneg<<<NB, 512>>>();
    k_final<<<1, 1>>>(out);
}

// round 3
// speedup vs baseline: 3.0561x; 1.4698x over previous
#include <cuda_runtime.h>
#include <stdint.h>

#define NB 64
#define NP 8732
#define NC 81
#define NO 32
#define THRESH 0.5f
#define NPR 3
#define MCH 16
#define MTH 256
#define PCHUNK ((NP + MCH - 1) / MCH)   // 546

// ---------------- device scratch (all zero-init, self-resetting) ----------------
__device__ unsigned long long g_key[NB * NO];   // packed (iou_bits<<32)|(0x7fffffff-p); 0 = empty
__device__ unsigned char g_obj[NB * NP];
__device__ unsigned char g_lab[NB * NP];
__device__ float g_ceneg[NB * NP];
__device__ int   g_npos[NB];
__device__ int   g_done[NB];
__device__ int   g_hbdone;
__device__ float g_loc_sum, g_pos_sum, g_hard_sum;
__device__ int   g_npos_total;

__device__ __forceinline__ float loc_term(const float4 pl, const float4 pr,
                                          float bx0, float by0, float bx1, float by1)
{
    const float cx = (bx0 + bx1) * 0.5f, cy = (by0 + by1) * 0.5f;
    const float w = bx1 - bx0, h = by1 - by0;
    const float g0 = (cx - pr.x) / (pr.z * 0.1f);
    const float g1 = (cy - pr.y) / (pr.w * 0.1f);
    const float g2 = logf(w / pr.z) * 5.0f;
    const float g3 = logf(h / pr.w) * 5.0f;
    return fabsf(pl.x - g0) + fabsf(pl.y - g1) + fabsf(pl.z - g2) + fabsf(pl.w - g3);
}

// ---------------- kernel 1: matching + loc loss + force-fix (fused) ----------------
__global__ __launch_bounds__(MTH) void k_match(
    const float4* __restrict__ priors4,   // [P] cxcy
    const float*  __restrict__ boxes,     // [B,O,4] xy
    const float4* __restrict__ predloc4,  // [B*P]
    const int*    __restrict__ labels_i32)
{
    __shared__ float s_bx0[NO], s_by0[NO], s_bx1[NO], s_by1[NO], s_ba[NO];
    __shared__ int s_lab[NO];
    __shared__ unsigned long long s_key[NO];
    __shared__ float s_rf[MTH / 32];
    __shared__ int   s_ri[MTH / 32];
    __shared__ int   s_last;

    const int b = blockIdx.y, chunk = blockIdx.x, tid = threadIdx.x;
    const bool lab64 = (labels_i32[1] == 0);
    if (tid < NO) {
        const float x0 = boxes[(b*NO+tid)*4+0], y0 = boxes[(b*NO+tid)*4+1];
        const float x1 = boxes[(b*NO+tid)*4+2], y1 = boxes[(b*NO+tid)*4+3];
        s_bx0[tid] = x0; s_by0[tid] = y0; s_bx1[tid] = x1; s_by1[tid] = y1;
        s_ba[tid] = (x1 - x0) * (y1 - y0);
        s_lab[tid] = lab64 ? labels_i32[(b*NO+tid)*2] : labels_i32[b*NO+tid];
        s_key[tid] = 0ull;
    }
    __syncthreads();

    const int p0 = chunk * PCHUNK;
    const int p1 = (p0 + PCHUNK < NP) ? p0 + PCHUNK : NP;
    float locsum = 0.f; int npos = 0;

    for (int p = p0 + tid; p < p1; p += MTH) {
        const float4 pr = priors4[p];
        const float px0 = pr.x - pr.z * 0.5f, py0 = pr.y - pr.w * 0.5f;
        const float px1 = pr.x + pr.z * 0.5f, py1 = pr.y + pr.w * 0.5f;
        const float parea = (px1 - px0) * (py1 - py0);
        const unsigned lowp = (unsigned)(0x7fffffff - p);
        float best = -1.f; int bi = 0;
        #pragma unroll 8
        for (int o = 0; o < NO; ++o) {
            float iw = fminf(s_bx1[o], px1) - fmaxf(s_bx0[o], px0); iw = fmaxf(iw, 0.f);
            float ih = fminf(s_by1[o], py1) - fmaxf(s_by0[o], py0); ih = fmaxf(ih, 0.f);
            const float inter = iw * ih;
            const float iou = __fdividef(inter, s_ba[o] + parea - inter);
            if (iou > best) { best = iou; bi = o; }   // strict > : first-max
            const unsigned long long key =
                ((unsigned long long)__float_as_uint(iou) << 32) | lowp;
            if (key > s_key[o]) atomicMax(&s_key[o], key);  // monotonic: stale read never skips
        }
        const int lab = (best < THRESH) ? 0 : s_lab[bi];
        g_lab[b*NP+p] = (unsigned char)lab;
        g_obj[b*NP+p] = (unsigned char)bi;
        if (lab != 0) {
            ++npos;
            locsum += loc_term(predloc4[b*NP+p], pr, s_bx0[bi], s_by0[bi], s_bx1[bi], s_by1[bi]);
        }
    }
    __syncthreads();
    if (tid < NO && s_key[tid] != 0ull) atomicMax(&g_key[b*NO+tid], s_key[tid]);

    // block reduce npos/locsum
    #pragma unroll
    for (int off = 16; off; off >>= 1) {
        locsum += __shfl_xor_sync(0xffffffffu, locsum, off);
        npos   += __shfl_xor_sync(0xffffffffu, npos, off);
    }
    if ((tid & 31) == 0) { s_rf[tid>>5] = locsum; s_ri[tid>>5] = npos; }
    __syncthreads();
    if (tid == 0) {
        float f = 0.f; int c = 0;
        #pragma unroll
        for (int i = 0; i < MTH/32; ++i) { f += s_rf[i]; c += s_ri[i]; }
        if (f != 0.f) atomicAdd(&g_loc_sum, f);
        if (c) { atomicAdd(&g_npos[b], c); atomicAdd(&g_npos_total, c); }
        __threadfence();
        const int old = atomicAdd(&g_done[b], 1);
        s_last = (old == MCH - 1);
    }
    __syncthreads();

    // last CTA of this batch applies the <=NO force-match corrections
    if (s_last && tid < 32) {
        __threadfence();
        const int lane = tid;
        const unsigned long long key = g_key[b*NO + lane];
        g_key[b*NO + lane] = 0ull;                 // reset for next replay
        if (lane == 0) g_done[b] = 0;
        const int p = 0x7fffffff - (int)(unsigned)(key & 0xffffffffull);
        const unsigned mm = __match_any_sync(0xffffffffu, p);
        float dloc = 0.f; int dnp = 0;
        if (lane == 31 - __clz(mm)) {              // last .at[].set wins -> highest o
            const int oldlab = g_lab[b*NP+p];
            g_lab[b*NP+p] = (unsigned char)s_lab[lane];
            const float4 pr = priors4[p];
            const float4 pl = predloc4[b*NP+p];
            dloc = loc_term(pl, pr, s_bx0[lane], s_by0[lane], s_bx1[lane], s_by1[lane]);
            if (oldlab != 0) {
                const int oo = g_obj[b*NP+p];
                dloc -= loc_term(pl, pr, s_bx0[oo], s_by0[oo], s_bx1[oo], s_by1[oo]);
            } else {
                dnp = 1;
            }
        }
        #pragma unroll
        for (int off = 16; off; off >>= 1) {
            dloc += __shfl_xor_sync(0xffffffffu, dloc, off);
            dnp  += __shfl_xor_sync(0xffffffffu, dnp, off);
        }
        if (lane == 0) {
            if (dloc != 0.f) atomicAdd(&g_loc_sum, dloc);
            if (dnp) { atomicAdd(&g_npos[b], dnp); atomicAdd(&g_npos_total, dnp); }
        }
    }
}

// ---------------- kernel 2: cross entropy, 2 rows per warp ----------------
__global__ __launch_bounds__(256) void k_ce(const float* __restrict__ scores)
{
    __shared__ float s_pos;
    const int tid = threadIdx.x, lane = tid & 31;
    if (tid == 0) s_pos = 0.f;
    __syncthreads();

    const int gw2 = (int)((blockIdx.x * blockDim.x + tid) >> 5);
    const int r0 = gw2 * 2;
    if (r0 < NB * NP) {
        const float* rp0 = scores + (size_t)r0 * NC;
        const float* rp1 = rp0 + NC;
        const float a0 = rp0[lane];
        const float a1 = rp0[lane + 32];
        const float a2 = (lane < NC - 64) ? rp0[lane + 64] : -3.0e38f;
        const float b0 = rp1[lane];
        const float b1 = rp1[lane + 32];
        const float b2 = (lane < NC - 64) ? rp1[lane + 64] : -3.0e38f;

        float m0 = fmaxf(fmaxf(a0, a1), a2);
        float m1 = fmaxf(fmaxf(b0, b1), b2);
        #pragma unroll
        for (int off = 16; off; off >>= 1) {
            m0 = fmaxf(m0, __shfl_xor_sync(0xffffffffu, m0, off));
            m1 = fmaxf(m1, __shfl_xor_sync(0xffffffffu, m1, off));
        }
        float s0 = __expf(a0 - m0) + __expf(a1 - m0) + ((lane < NC - 64) ? __expf(a2 - m0) : 0.f);
        float s1 = __expf(b0 - m1) + __expf(b1 - m1) + ((lane < NC - 64) ? __expf(b2 - m1) : 0.f);
        #pragma unroll
        for (int off = 16; off; off >>= 1) {
            s0 += __shfl_xor_sync(0xffffffffu, s0, off);
            s1 += __shfl_xor_sync(0xffffffffu, s1, off);
        }
        const int l0 = g_lab[r0], l1 = g_lab[r0 + 1];
        float sl0, sl1;
        if (l0 < 32)      sl0 = __shfl_sync(0xffffffffu, a0, l0);
        else if (l0 < 64) sl0 = __shfl_sync(0xffffffffu, a1, l0 - 32);
        else              sl0 = __shfl_sync(0xffffffffu, a2, l0 - 64);
        if (l1 < 32)      sl1 = __shfl_sync(0xffffffffu, b0, l1);
        else if (l1 < 64) sl1 = __shfl_sync(0xffffffffu, b1, l1 - 32);
        else              sl1 = __shfl_sync(0xffffffffu, b2, l1 - 64);
        const float ce0 = m0 + __logf(s0) - sl0;
        const float ce1 = m1 + __logf(s1) - sl1;
        if (lane == 0) {
            g_ceneg[r0]     = (l0 != 0) ? 0.f : ce0;
            g_ceneg[r0 + 1] = (l1 != 0) ? 0.f : ce1;
            const float pp = ((l0 != 0) ? ce0 : 0.f) + ((l1 != 0) ? ce1 : 0.f);
            if (pp != 0.f) atomicAdd(&s_pos, pp);
        }
    }
    __syncthreads();
    if (tid == 0 && s_pos != 0.f) atomicAdd(&g_pos_sum, s_pos);
}

// ---------------- kernel 3: exact top-k sum via radix select + fused finalize ----------------
__global__ __launch_bounds__(512) void k_hardneg(float* __restrict__ out)
{
    __shared__ float s_ce[NP];
    __shared__ int s_cnt[256];
    __shared__ unsigned sh_prefix;
    __shared__ int sh_rem, sh_k;
    __shared__ float s_r[16];

    const int b = blockIdx.x, tid = threadIdx.x, nt = 512, lane = tid & 31;
    for (int p = tid; p < NP; p += nt) s_ce[p] = g_ceneg[b*NP+p];
    if (tid == 0) {
        sh_k = NPR * g_npos[b];
        g_npos[b] = 0;                 // reset for next replay
        sh_prefix = 0u; sh_rem = sh_k;
    }
    __syncthreads();
    const int k = sh_k;

    if (k > 0 && k < NP) {
        for (int shift = 24; shift >= 0; shift -= 8) {
            const unsigned pref = sh_prefix;
            const int rem = sh_rem;
            const unsigned hm = (shift == 24) ? 0u : (0xffffffffu << (shift + 8));
            if (tid < 256) s_cnt[tid] = 0;
            __syncthreads();
            for (int base = 0; base < NP; base += nt) {
                const int p = base + tid;
                unsigned bin = 0xffffffffu;
                if (p < NP) {
                    const unsigned bits = __float_as_uint(s_ce[p]);
                    if ((bits & hm) == pref) bin = (bits >> shift) & 255u;
                }
                const unsigned mm = __match_any_sync(0xffffffffu, bin);
                if (bin != 0xffffffffu && lane == (unsigned)(__ffs(mm) - 1))
                    atomicAdd(&s_cnt[bin], __popc(mm));
            }
            __syncthreads();
            for (int off = 1; off < 256; off <<= 1) {   // suffix scan
                int c = 0;
                if (tid < 256) { c = s_cnt[tid]; if (tid + off < 256) c += s_cnt[tid + off]; }
                __syncthreads();
                if (tid < 256) s_cnt[tid] = c;
                __syncthreads();
            }
            if (tid < 256) {
                const int ge = s_cnt[tid];
                const int gt = (tid < 255) ? s_cnt[tid + 1] : 0;
                if (ge >= rem && gt < rem) {
                    sh_rem = rem - gt;
                    sh_prefix = pref | ((unsigned)tid << shift);
                }
            }
            __syncthreads();
        }
        const float kth = __uint_as_float(sh_prefix);
        const int rem = sh_rem;
        float acc = 0.f;
        for (int p = tid; p < NP; p += nt) { const float v = s_ce[p]; if (v > kth) acc += v; }
        #pragma unroll
        for (int off = 16; off; off >>= 1) acc += __shfl_xor_sync(0xffffffffu, acc, off);
        if (lane == 0) s_r[tid >> 5] = acc;
        __syncthreads();
        if (tid == 0) {
            float t = (float)rem * kth;
            #pragma unroll
            for (int i = 0; i < 16; ++i) t += s_r[i];
            atomicAdd(&g_hard_sum, t);
        }
    } else if (k >= NP) {
        float acc = 0.f;
        for (int p = tid; p < NP; p += nt) acc += s_ce[p];
        #pragma unroll
        for (int off = 16; off; off >>= 1) acc += __shfl_xor_sync(0xffffffffu, acc, off);
        if (lane == 0) s_r[tid >> 5] = acc;
        __syncthreads();
        if (tid == 0) {
            float t = 0.f;
            #pragma unroll
            for (int i = 0; i < 16; ++i) t += s_r[i];
            atomicAdd(&g_hard_sum, t);
        }
    }

    // fused finalize: last CTA computes the loss and resets accumulators
    __syncthreads();
    if (tid == 0) {
        __threadfence();
        const int old = atomicAdd(&g_hbdone, 1);
        if (old == NB - 1) {
            __threadfence();
            const float np = (float)g_npos_total;
            out[0] = (g_hard_sum + g_pos_sum) / np + g_loc_sum / (np * 4.0f);
            g_loc_sum = 0.f; g_pos_sum = 0.f; g_hard_sum = 0.f;
            g_npos_total = 0; g_hbdone = 0;
        }
    }
}

// ---------------- launch ----------------
extern "C" void kernel_launch(void* const* d_in, const int* in_sizes, int n_in,
                              void* d_out, int out_size)
{
    const float* pred_locs   = (const float*)d_in[0];
    const float* pred_scores = (const float*)d_in[1];
    const float* boxes       = (const float*)d_in[2];
    const int*   labels      = (const int*)d_in[3];
    const float* priors      = (const float*)d_in[4];
    float* out = (float*)d_out;

    dim3 mg(MCH, NB);
    k_match<<<mg, MTH>>>((const float4*)priors, boxes, (const float4*)pred_locs, labels);
    const int warps2 = (NB * NP) / 2;
    k_ce<<<(warps2 * 32 + 255) / 256, 256>>>(pred_scores);
    k_hardneg<<<NB, 512>>>(out);
}

// round 4
// speedup vs baseline: 3.4330x; 1.1233x over previous
#include <cuda_runtime.h>
#include <stdint.h>

#define NB 64
#define NP 8732
#define NC 81
#define NO 32
#define THRESH 0.5f
#define NPR 3
#define MCH 16
#define MTH 256
#define PCHUNK ((NP + MCH - 1) / MCH)   // 546

// ---------------- device scratch (all zero-init, self-resetting) ----------------
__device__ unsigned long long g_key[NB * NO];   // packed (iou_bits<<32)|(0x7fffffff-p); 0 = empty
__device__ unsigned char g_obj[NB * NP];
__device__ unsigned char g_lab[NB * NP];
__device__ float g_ceneg[NB * NP];
__device__ int   g_npos[NB];
__device__ int   g_done[NB];
__device__ int   g_hbdone;
__device__ float g_loc_sum, g_pos_sum, g_hard_sum;
__device__ int   g_npos_total;

__device__ __forceinline__ float loc_term(const float4 pl, const float4 pr,
                                          float bx0, float by0, float bx1, float by1)
{
    const float cx = (bx0 + bx1) * 0.5f, cy = (by0 + by1) * 0.5f;
    const float w = bx1 - bx0, h = by1 - by0;
    const float g0 = (cx - pr.x) / (pr.z * 0.1f);
    const float g1 = (cy - pr.y) / (pr.w * 0.1f);
    const float g2 = logf(w / pr.z) * 5.0f;
    const float g3 = logf(h / pr.w) * 5.0f;
    return fabsf(pl.x - g0) + fabsf(pl.y - g1) + fabsf(pl.z - g2) + fabsf(pl.w - g3);
}

// ---------------- kernel 1: matching + loc loss + force-fix (fused) ----------------
__global__ __launch_bounds__(MTH) void k_match(
    const float4* __restrict__ priors4,   // [P] cxcy
    const float*  __restrict__ boxes,     // [B,O,4] xy
    const float4* __restrict__ predloc4,  // [B*P]
    const int*    __restrict__ labels_i32)
{
    __shared__ float4 s_box[NO];          // (x0,y0,x1,y1)
    __shared__ float  s_ba[NO];
    __shared__ int s_lab[NO];
    __shared__ unsigned long long s_key[NO];
    __shared__ float s_rf[MTH / 32];
    __shared__ int   s_ri[MTH / 32];
    __shared__ int   s_last;

    const int b = blockIdx.y, chunk = blockIdx.x, tid = threadIdx.x;
    const bool lab64 = (labels_i32[1] == 0);
    if (tid < NO) {
        const float x0 = boxes[(b*NO+tid)*4+0], y0 = boxes[(b*NO+tid)*4+1];
        const float x1 = boxes[(b*NO+tid)*4+2], y1 = boxes[(b*NO+tid)*4+3];
        s_box[tid] = make_float4(x0, y0, x1, y1);
        s_ba[tid] = (x1 - x0) * (y1 - y0);
        s_lab[tid] = lab64 ? labels_i32[(b*NO+tid)*2] : labels_i32[b*NO+tid];
        s_key[tid] = 0ull;
    }
    __syncthreads();

    const int p0 = chunk * PCHUNK;
    const int p1 = (p0 + PCHUNK < NP) ? p0 + PCHUNK : NP;
    float locsum = 0.f; int npos = 0;

    for (int p = p0 + tid; p < p1; p += MTH) {
        const float4 pr = priors4[p];
        const float px0 = pr.x - pr.z * 0.5f, py0 = pr.y - pr.w * 0.5f;
        const float px1 = pr.x + pr.z * 0.5f, py1 = pr.y + pr.w * 0.5f;
        const float parea = (px1 - px0) * (py1 - py0);
        const unsigned lowp = (unsigned)(0x7fffffff - p);
        float best = 0.f; int bi = 0;
        #pragma unroll 8
        for (int o = 0; o < NO; ++o) {
            const float4 bx = s_box[o];
            const float iw = fminf(bx.z, px1) - fmaxf(bx.x, px0);
            const float ih = fminf(bx.w, py1) - fmaxf(bx.y, py0);
            if (iw > 0.f && ih > 0.f) {           // ~87% of pairs skip everything
                const float inter = iw * ih;
                const float iou = __fdividef(inter, s_ba[o] + parea - inter);
                if (iou > best) { best = iou; bi = o; }   // strict > : first-max
                const unsigned long long key =
                    ((unsigned long long)__float_as_uint(iou) << 32) | lowp;
                if (key > s_key[o]) atomicMax(&s_key[o], key);  // monotonic
            }
        }
        const int lab = (best < THRESH) ? 0 : s_lab[bi];
        g_lab[b*NP+p] = (unsigned char)lab;
        g_obj[b*NP+p] = (unsigned char)bi;
        if (lab != 0) {
            ++npos;
            const float4 bb = s_box[bi];
            locsum += loc_term(predloc4[b*NP+p], pr, bb.x, bb.y, bb.z, bb.w);
        }
    }
    __syncthreads();
    if (tid < NO && s_key[tid] != 0ull) atomicMax(&g_key[b*NO+tid], s_key[tid]);

    // block reduce npos/locsum
    #pragma unroll
    for (int off = 16; off; off >>= 1) {
        locsum += __shfl_xor_sync(0xffffffffu, locsum, off);
        npos   += __shfl_xor_sync(0xffffffffu, npos, off);
    }
    if ((tid & 31) == 0) { s_rf[tid>>5] = locsum; s_ri[tid>>5] = npos; }
    __syncthreads();
    if (tid == 0) {
        float f = 0.f; int c = 0;
        #pragma unroll
        for (int i = 0; i < MTH/32; ++i) { f += s_rf[i]; c += s_ri[i]; }
        if (f != 0.f) atomicAdd(&g_loc_sum, f);
        if (c) { atomicAdd(&g_npos[b], c); atomicAdd(&g_npos_total, c); }
        __threadfence();
        const int old = atomicAdd(&g_done[b], 1);
        s_last = (old == MCH - 1);
    }
    __syncthreads();

    // last CTA of this batch applies the <=NO force-match corrections
    if (s_last && tid < 32) {
        __threadfence();
        const int lane = tid;
        const unsigned long long key = g_key[b*NO + lane];
        g_key[b*NO + lane] = 0ull;                 // reset for next replay
        if (lane == 0) g_done[b] = 0;
        const int p = 0x7fffffff - (int)(unsigned)(key & 0xffffffffull);
        const unsigned mm = __match_any_sync(0xffffffffu, p);
        float dloc = 0.f; int dnp = 0;
        if ((unsigned)p < NP && lane == 31 - __clz(mm)) {  // last .at[].set wins -> highest o
            const int oldlab = g_lab[b*NP+p];
            g_lab[b*NP+p] = (unsigned char)s_lab[lane];
            const float4 pr = priors4[p];
            const float4 pl = predloc4[b*NP+p];
            const float4 bb = s_box[lane];
            dloc = loc_term(pl, pr, bb.x, bb.y, bb.z, bb.w);
            if (oldlab != 0) {
                const int oo = g_obj[b*NP+p];
                const float4 ob = s_box[oo];
                dloc -= loc_term(pl, pr, ob.x, ob.y, ob.z, ob.w);
            } else {
                dnp = 1;
            }
        }
        #pragma unroll
        for (int off = 16; off; off >>= 1) {
            dloc += __shfl_xor_sync(0xffffffffu, dloc, off);
            dnp  += __shfl_xor_sync(0xffffffffu, dnp, off);
        }
        if (lane == 0) {
            if (dloc != 0.f) atomicAdd(&g_loc_sum, dloc);
            if (dnp) { atomicAdd(&g_npos[b], dnp); atomicAdd(&g_npos_total, dnp); }
        }
    }
}

// ---------------- kernel 2: cross entropy, 4 rows per warp ----------------
__global__ __launch_bounds__(256) void k_ce(const float* __restrict__ scores)
{
    __shared__ float s_pos;
    const int tid = threadIdx.x, lane = tid & 31;
    if (tid == 0) s_pos = 0.f;
    __syncthreads();

    const int gw = (int)((blockIdx.x * blockDim.x + tid) >> 5);
    const int r0 = gw * 4;
    if (r0 < NB * NP) {
        float x0[4], x1[4], x2[4];
        const bool hi = (lane < NC - 64);
        #pragma unroll
        for (int r = 0; r < 4; ++r) {
            const float* rp = scores + (size_t)(r0 + r) * NC;
            x0[r] = rp[lane];
            x1[r] = rp[lane + 32];
            x2[r] = hi ? rp[lane + 64] : -3.0e38f;
        }
        float m[4], s[4];
        #pragma unroll
        for (int r = 0; r < 4; ++r) m[r] = fmaxf(fmaxf(x0[r], x1[r]), x2[r]);
        #pragma unroll
        for (int off = 16; off; off >>= 1) {
            #pragma unroll
            for (int r = 0; r < 4; ++r)
                m[r] = fmaxf(m[r], __shfl_xor_sync(0xffffffffu, m[r], off));
        }
        #pragma unroll
        for (int r = 0; r < 4; ++r)
            s[r] = __expf(x0[r]-m[r]) + __expf(x1[r]-m[r]) + (hi ? __expf(x2[r]-m[r]) : 0.f);
        #pragma unroll
        for (int off = 16; off; off >>= 1) {
            #pragma unroll
            for (int r = 0; r < 4; ++r)
                s[r] += __shfl_xor_sync(0xffffffffu, s[r], off);
        }
        const uchar4 lv = *(const uchar4*)(g_lab + r0);
        const int l[4] = {lv.x, lv.y, lv.z, lv.w};
        float ceneg[4]; float pp = 0.f;
        #pragma unroll
        for (int r = 0; r < 4; ++r) {
            float sl;
            if (l[r] < 32)      sl = __shfl_sync(0xffffffffu, x0[r], l[r]);
            else if (l[r] < 64) sl = __shfl_sync(0xffffffffu, x1[r], l[r] - 32);
            else                sl = __shfl_sync(0xffffffffu, x2[r], l[r] - 64);
            const float ce = m[r] + __logf(s[r]) - sl;
            if (l[r] != 0) { pp += ce; ceneg[r] = 0.f; }
            else           { ceneg[r] = ce; }
        }
        if (lane == 0) {
            *(float4*)(g_ceneg + r0) = make_float4(ceneg[0], ceneg[1], ceneg[2], ceneg[3]);
            if (pp != 0.f) atomicAdd(&s_pos, pp);
        }
    }
    __syncthreads();
    if (tid == 0 && s_pos != 0.f) atomicAdd(&g_pos_sum, s_pos);
}

// ---------------- kernel 3: exact top-k sum via radix select + fused finalize ----------------
__global__ __launch_bounds__(512) void k_hardneg(float* __restrict__ out)
{
    __shared__ float s_ce[NP];
    __shared__ int s_cnt[256];
    __shared__ unsigned sh_prefix;
    __shared__ int sh_rem, sh_k;
    __shared__ float s_r[16];

    const int b = blockIdx.x, tid = threadIdx.x, nt = 512, lane = tid & 31;
    for (int i = tid; i < NP / 4; i += nt)
        *(float4*)(s_ce + i * 4) = *(const float4*)(g_ceneg + b*NP + i * 4);
    if (tid == 0) {
        sh_k = NPR * g_npos[b];
        g_npos[b] = 0;                 // reset for next replay
        sh_prefix = 0u; sh_rem = sh_k;
    }
    __syncthreads();
    const int k = sh_k;

    if (k > 0 && k < NP) {
        for (int shift = 24; shift >= 0; shift -= 8) {
            const unsigned pref = sh_prefix;
            const int rem = sh_rem;
            const unsigned hm = (shift == 24) ? 0u : (0xffffffffu << (shift + 8));
            if (tid < 256) s_cnt[tid] = 0;
            __syncthreads();
            for (int base = 0; base < NP; base += nt) {
                const int p = base + tid;
                unsigned bin = 0xffffffffu;
                if (p < NP) {
                    const unsigned bits = __float_as_uint(s_ce[p]);
                    if ((bits & hm) == pref) bin = (bits >> shift) & 255u;
                }
                const unsigned mm = __match_any_sync(0xffffffffu, bin);
                if (bin != 0xffffffffu && lane == (unsigned)(__ffs(mm) - 1))
                    atomicAdd(&s_cnt[bin], __popc(mm));
            }
            __syncthreads();
            for (int off = 1; off < 256; off <<= 1) {   // suffix scan
                int c = 0;
                if (tid < 256) { c = s_cnt[tid]; if (tid + off < 256) c += s_cnt[tid + off]; }
                __syncthreads();
                if (tid < 256) s_cnt[tid] = c;
                __syncthreads();
            }
            if (tid < 256) {
                const int ge = s_cnt[tid];
                const int gt = (tid < 255) ? s_cnt[tid + 1] : 0;
                if (ge >= rem && gt < rem) {
                    sh_rem = rem - gt;
                    sh_prefix = pref | ((unsigned)tid << shift);
                }
            }
            __syncthreads();
        }
        const float kth = __uint_as_float(sh_prefix);
        const int rem = sh_rem;
        float acc = 0.f;
        for (int p = tid; p < NP; p += nt) { const float v = s_ce[p]; if (v > kth) acc += v; }
        #pragma unroll
        for (int off = 16; off; off >>= 1) acc += __shfl_xor_sync(0xffffffffu, acc, off);
        if (lane == 0) s_r[tid >> 5] = acc;
        __syncthreads();
        if (tid == 0) {
            float t = (float)rem * kth;
            #pragma unroll
            for (int i = 0; i < 16; ++i) t += s_r[i];
            atomicAdd(&g_hard_sum, t);
        }
    } else if (k >= NP) {
        float acc = 0.f;
        for (int p = tid; p < NP; p += nt) acc += s_ce[p];
        #pragma unroll
        for (int off = 16; off; off >>= 1) acc += __shfl_xor_sync(0xffffffffu, acc, off);
        if (lane == 0) s_r[tid >> 5] = acc;
        __syncthreads();
        if (tid == 0) {
            float t = 0.f;
            #pragma unroll
            for (int i = 0; i < 16; ++i) t += s_r[i];
            atomicAdd(&g_hard_sum, t);
        }
    }

    // fused finalize: last CTA computes the loss and resets accumulators
    __syncthreads();
    if (tid == 0) {
        __threadfence();
        const int old = atomicAdd(&g_hbdone, 1);
        if (old == NB - 1) {
            __threadfence();
            const float np = (float)g_npos_total;
            out[0] = (g_hard_sum + g_pos_sum) / np + g_loc_sum / (np * 4.0f);
            g_loc_sum = 0.f; g_pos_sum = 0.f; g_hard_sum = 0.f;
            g_npos_total = 0; g_hbdone = 0;
        }
    }
}

// ---------------- launch ----------------
extern "C" void kernel_launch(void* const* d_in, const int* in_sizes, int n_in,
                              void* d_out, int out_size)
{
    const float* pred_locs   = (const float*)d_in[0];
    const float* pred_scores = (const float*)d_in[1];
    const float* boxes       = (const float*)d_in[2];
    const int*   labels      = (const int*)d_in[3];
    const float* priors      = (const float*)d_in[4];
    float* out = (float*)d_out;

    dim3 mg(MCH, NB);
    k_match<<<mg, MTH>>>((const float4*)priors, boxes, (const float4*)pred_locs, labels);
    const int warps4 = (NB * NP + 3) / 4;
    k_ce<<<(warps4 * 32 + 255) / 256, 256>>>(pred_scores);
    k_hardneg<<<NB, 512>>>(out);
}